// round 8
// baseline (speedup 1.0000x reference)
#include <cuda_runtime.h>
#include <cstdint>
#include <cstddef>

// CRF log-likelihood: sum_b (log_num - log_den), scaled forward algorithm.
//   p_t[j] = (sum_i p_{t-1}[i] * E[i][j]) * exp(emit_t[j]),  E = exp(transitions)
//   alpha_t = C + log p_t ; rescale every 8 steps.
// R8: DUAL-BATCH PER WARP — two independent batches interleaved in one warp's
//     instruction stream (intra-warp ILP hides chain latency; E regs shared;
//     no cross-warp sync). 128 blocks x 4 warps = 512 warps, 1/SMSP, one wave.
//     Launch cycle is [fwd, reduce] so ncu -s 5 lands on fwd.

#define T_FIXED 512
#define NK2 26          // packed (i,i+1) pairs covering i=0..51 (zero-padded)
#define BMAX 1024

typedef unsigned long long u64;

__device__ __forceinline__ u64 ffma2(u64 a, u64 b, u64 c) {
    u64 d; asm("fma.rn.f32x2 %0, %1, %2, %3;" : "=l"(d) : "l"(a), "l"(b), "l"(c));
    return d;
}
__device__ __forceinline__ u64 add2(u64 a, u64 b) {
    u64 d; asm("add.rn.f32x2 %0, %1, %2;" : "=l"(d) : "l"(a), "l"(b));
    return d;
}
__device__ __forceinline__ u64 pack2(float lo, float hi) {
    u64 d; asm("mov.b64 %0, {%1, %2};" : "=l"(d) : "f"(lo), "f"(hi));
    return d;
}
__device__ __forceinline__ float2 unpack2f(u64 v) {
    float2 r; asm("mov.b64 {%0, %1}, %2;" : "=f"(r.x), "=f"(r.y) : "l"(v));
    return r;
}

__device__ float g_res[BMAX];

__global__ __launch_bounds__(128) void fwd_kernel(
    const float* __restrict__ logits, const float* __restrict__ trans,
    const float* __restrict__ st, const float* __restrict__ en,
    const int* __restrict__ tags, const int* __restrict__ mask,
    int B, int K) {
    const int T = T_FIXED;
    const int lane = threadIdx.x & 31;
    const int warp = threadIdx.x >> 5;
    const int bA = (blockIdx.x * 4 + warp) * 2;   // this warp's two batches
    const int bB = bA + 1;
    __shared__ __align__(16) float psh[4][2][2][64];  // [warp][batch][buf][i]
    if (bB >= B + 1) return;   // B=1024: never taken, keeps generality

    // E columns j0=2*lane, j1=2*lane+1 packed over i-pairs (shared by both batches)
    const int o2 = 2 * lane;
    const bool valid = (o2 + 1 < K) && (o2 < K);  // K even: both cols or neither
    const int jc = valid ? o2 : 0;

    u64 EA[NK2], EB[NK2];
#pragma unroll
    for (int k = 0; k < NK2; k++) {
        int i0 = 2 * k, i1 = 2 * k + 1;
        int i0c = (i0 < K) ? i0 : 0, i1c = (i1 < K) ? i1 : 0;
        float ea0 = __expf(__ldg(trans + i0c * K + jc));
        float ea1 = __expf(__ldg(trans + i1c * K + jc));
        float eb0 = __expf(__ldg(trans + i0c * K + jc + 1));
        float eb1 = __expf(__ldg(trans + i1c * K + jc + 1));
        bool v0 = valid && (i0 < K), v1 = valid && (i1 < K);
        EA[k] = pack2(v0 ? ea0 : 0.f, v1 ? ea1 : 0.f);
        EB[k] = pack2(v0 ? eb0 : 0.f, v1 ? eb1 : 0.f);
    }
    float es0 = valid ? __expf(st[jc]) : 0.f;
    float es1 = valid ? __expf(st[jc + 1]) : 0.f;
    float ee0 = valid ? __expf(en[jc]) : 0.f;
    float ee1 = valid ? __expf(en[jc + 1]) : 0.f;
    if (!valid) { es0 = es1 = ee0 = ee1 = 0.f; }

    const float* lrowA = logits + (size_t)bA * T * K;
    const float* lrowB = logits + (size_t)bB * T * K;
    const int* mrowA = mask + (size_t)bA * T;
    const int* mrowB = mask + (size_t)bB * T;

    float* const pA0 = psh[warp][0][0];
    float* const pA1 = psh[warp][0][1];
    float* const pB0 = psh[warp][1][0];
    float* const pB1 = psh[warp][1][1];

    // t = 0 for both batches
    float wA0, wA1, wB0, wB1;
    {
        float2 ea = *(const float2*)(lrowA + jc);
        float2 eb = *(const float2*)(lrowB + jc);
        wA0 = es0 * __expf(ea.x);  wA1 = es1 * __expf(ea.y);
        wB0 = es0 * __expf(eb.x);  wB1 = es1 * __expf(eb.y);
    }
    *(float2*)(pA0 + o2) = make_float2(wA0, wA1);
    *(float2*)(pB0 + o2) = make_float2(wB0, wB1);
    float CA = 0.f, CB = 0.f;
    __syncwarp();

    // depth-4 prefetch rings (static register slots) for both batches
    float2 eA0s = *(const float2*)(lrowA + (size_t)1 * K + jc);
    float2 eA1s = *(const float2*)(lrowA + (size_t)2 * K + jc);
    float2 eA2s = *(const float2*)(lrowA + (size_t)3 * K + jc);
    float2 eA3s = *(const float2*)(lrowA + (size_t)4 * K + jc);
    float2 eB0s = *(const float2*)(lrowB + (size_t)1 * K + jc);
    float2 eB1s = *(const float2*)(lrowB + (size_t)2 * K + jc);
    float2 eB2s = *(const float2*)(lrowB + (size_t)3 * K + jc);
    float2 eB3s = *(const float2*)(lrowB + (size_t)4 * K + jc);
    int mA0s = mrowA[1], mA1s = mrowA[2], mA2s = mrowA[3], mA3s = mrowA[4];
    int mB0s = mrowB[1], mB1s = mrowB[2], mB2s = mrowB[3], mB3s = mrowB[4];

#define STEP(tt, EAS, EBS, MAS, MBS, RA, RB_, WA, WB_)                         \
    {                                                                          \
        const int t_ = (tt);                                                   \
        float2 eA_ = EAS; float2 eB_ = EBS;                                    \
        int mA_ = MAS;    int mB_ = MBS;                                       \
        if (t_ + 4 < T) {                                                      \
            EAS = *(const float2*)(lrowA + (size_t)(t_ + 4) * K + jc);         \
            EBS = *(const float2*)(lrowB + (size_t)(t_ + 4) * K + jc);         \
            MAS = mrowA[t_ + 4];                                               \
            MBS = mrowB[t_ + 4];                                               \
        }                                                                      \
        float xA0_ = __expf(eA_.x), xA1_ = __expf(eA_.y);                      \
        float xB0_ = __expf(eB_.x), xB1_ = __expf(eB_.y);                      \
        const ulonglong2* ra_ = (const ulonglong2*)(RA);                       \
        const ulonglong2* rb_ = (const ulonglong2*)(RB_);                      \
        u64 aA0 = 0, aA1 = 0, aA2 = 0, aA3 = 0;                                \
        u64 aB0 = 0, aB1 = 0, aB2 = 0, aB3 = 0;                                \
        _Pragma("unroll")                                                      \
        for (int q = 0; q < 13; q++) {                                         \
            ulonglong2 pva = ra_[q];                                           \
            ulonglong2 pvb = rb_[q];                                           \
            aA0 = ffma2(pva.x, EA[2 * q], aA0);                                \
            aB0 = ffma2(pvb.x, EA[2 * q], aB0);                                \
            aA1 = ffma2(pva.y, EA[2 * q + 1], aA1);                            \
            aB1 = ffma2(pvb.y, EA[2 * q + 1], aB1);                            \
            aA2 = ffma2(pva.x, EB[2 * q], aA2);                                \
            aB2 = ffma2(pvb.x, EB[2 * q], aB2);                                \
            aA3 = ffma2(pva.y, EB[2 * q + 1], aA3);                            \
            aB3 = ffma2(pvb.y, EB[2 * q + 1], aB3);                            \
        }                                                                      \
        float2 sA0 = unpack2f(add2(aA0, aA1));                                 \
        float2 sA1 = unpack2f(add2(aA2, aA3));                                 \
        float2 sB0 = unpack2f(add2(aB0, aB1));                                 \
        float2 sB1 = unpack2f(add2(aB2, aB3));                                 \
        float nA0 = (sA0.x + sA0.y) * xA0_;                                    \
        float nA1 = (sA1.x + sA1.y) * xA1_;                                    \
        float nB0 = (sB0.x + sB0.y) * xB0_;                                    \
        float nB1 = (sB1.x + sB1.y) * xB1_;                                    \
        wA0 = mA_ ? nA0 : wA0;  wA1 = mA_ ? nA1 : wA1;                         \
        wB0 = mB_ ? nB0 : wB0;  wB1 = mB_ ? nB1 : wB1;                         \
        *(float2*)((WA) + o2) = make_float2(wA0, wA1);                         \
        *(float2*)((WB_) + o2) = make_float2(wB0, wB1);                        \
        __syncwarp();                                                          \
        if ((t_ & 7) == 7) {                                                   \
            float srA = wA0 + wA1, srB = wB0 + wB1;                            \
            _Pragma("unroll")                                                  \
            for (int off = 16; off > 0; off >>= 1) {                           \
                srA += __shfl_xor_sync(0xffffffffu, srA, off);                 \
                srB += __shfl_xor_sync(0xffffffffu, srB, off);                 \
            }                                                                  \
            CA += __logf(srA);  CB += __logf(srB);                             \
            float iA = __frcp_rn(srA), iB = __frcp_rn(srB);                    \
            wA0 *= iA; wA1 *= iA; wB0 *= iB; wB1 *= iB;                        \
            *(float2*)((WA) + o2) = make_float2(wA0, wA1);                     \
            *(float2*)((WB_) + o2) = make_float2(wB0, wB1);                    \
            __syncwarp();                                                      \
        }                                                                      \
    }

    int t = 1;
    for (; t + 3 < T; t += 4) {          // t odd at loop head: parity static
        STEP(t + 0, eA0s, eB0s, mA0s, mB0s, pA0, pB0, pA1, pB1)
        STEP(t + 1, eA1s, eB1s, mA1s, mB1s, pA1, pB1, pA0, pB0)
        STEP(t + 2, eA2s, eB2s, mA2s, mB2s, pA0, pB0, pA1, pB1)
        STEP(t + 3, eA3s, eB3s, mA3s, mB3s, pA1, pB1, pA0, pB0)
    }
    if (t + 2 < T) {                      // T=512: tail t = 509,510,511
        STEP(t + 0, eA0s, eB0s, mA0s, mB0s, pA0, pB0, pA1, pB1)
        STEP(t + 1, eA1s, eB1s, mA1s, mB1s, pA1, pB1, pA0, pB0)
        STEP(t + 2, eA2s, eB2s, mA2s, mB2s, pA0, pB0, pA1, pB1)
    }
#undef STEP

    // den = C + log( sum_j w[j] * exp(end[j]) ) for both batches
    float srA = wA0 * ee0 + wA1 * ee1;
    float srB = wB0 * ee0 + wB1 * ee1;
#pragma unroll
    for (int off = 16; off > 0; off >>= 1) {
        srA += __shfl_xor_sync(0xffffffffu, srA, off);
        srB += __shfl_xor_sync(0xffffffffu, srB, off);
    }
    const float denA = CA + __logf(srA);
    const float denB = CB + __logf(srB);

    // fused numerator, one batch at a time (cheap)
#pragma unroll
    for (int bi = 0; bi < 2; bi++) {
        const int b_ = bA + bi;
        const float den_ = bi ? denB : denA;
        const int* trow = tags + (size_t)b_ * T;
        const int* mrw = bi ? mrowB : mrowA;
        const float* lrw = bi ? lrowB : lrowA;
        float acc = 0.f;
        int msum = 0;
        for (int tt = lane; tt < T; tt += 32) {
            int tg = trow[tt];
            int mi = mrw[tt];
            float mf = (float)mi;
            msum += mi;
            if (tt >= 1)     acc += __ldg(trans + trow[tt - 1] * K + tg) * mf;
            if (tt < T - 1)  acc += lrw[(size_t)tt * K + tg] * mf;
        }
#pragma unroll
        for (int off = 16; off > 0; off >>= 1) {
            acc  += __shfl_xor_sync(0xffffffffu, acc, off);
            msum += __shfl_xor_sync(0xffffffffu, msum, off);
        }
        if (lane == 0) {
            int last = msum - 1;
            if (last < 0) last += T;        // jnp wrap-around on index -1
            int lt = trow[last];
            float sc = acc + st[trow[0]] + en[lt]
                     + lrw[(size_t)(T - 1) * K + lt] * (float)mrw[T - 1];
            g_res[b_] = sc - den_;
        }
    }
}

__global__ void reduce_kernel(float* __restrict__ out, int B) {
    __shared__ double sd[256];
    int tid = threadIdx.x;
    double s = 0.0;
    for (int i = tid; i < B; i += 256) s += (double)g_res[i];
    sd[tid] = s;
    __syncthreads();
    for (int k = 128; k > 0; k >>= 1) {
        if (tid < k) sd[tid] += sd[tid + k];
        __syncthreads();
    }
    if (tid == 0) out[0] = (float)sd[0];
}

extern "C" void kernel_launch(void* const* d_in, const int* in_sizes, int n_in,
                              void* d_out, int out_size) {
    const float* logits = (const float*)d_in[0];
    const float* trans  = (const float*)d_in[1];
    const float* st     = (const float*)d_in[2];
    const float* en     = (const float*)d_in[3];
    const int*   tags   = (const int*)d_in[4];
    const int*   mask   = (const int*)d_in[5];

    int K  = in_sizes[2];        // 50
    int BT = in_sizes[4];        // B*T
    int B  = BT / T_FIXED;       // 1024

    // 2-launch cycle: with the harness's one pre-launch, ncu -s 5 lands on fwd
    fwd_kernel<<<128, 128>>>(logits, trans, st, en, tags, mask, B, K);
    reduce_kernel<<<1, 256>>>((float*)d_out, B);
}

// round 9
// speedup vs baseline: 1.9284x; 1.9284x over previous
#include <cuda_runtime.h>
#include <cuda_bf16.h>
#include <cstdint>
#include <cstddef>

// CRF log-likelihood: sum_b (log_num - log_den), scaled forward algorithm.
//   p_t[j] = (sum_i p_{t-1}[i] * E[i][j]) * exp(emit_t[j]),  E = exp(transitions)
//   alpha_t = C + log p_t ; rescale every 8 steps (fp32 bookkeeping).
// R9: matvec in bf16 HFMA2 (rt 2 => 2x MAC throughput vs f32x2 at rt 4).
//     p stored in shared as bf16x2 (i-pairs): 6 LDS.128 + 1 LDS.64 per step.
//     w / rescale / exp / numerator all remain fp32. R5's proven mapping:
//     1 warp = 1 batch, 128 blocks x 8 warps, depth-4 prefetch, fused num.

#define T_FIXED 512
#define NK2 26          // (i,i+1) bf16x2 pairs covering i=0..51 (zero-padded)
#define BMAX 1024
#define NW 8

typedef __nv_bfloat162 bf2;

__device__ float g_res[BMAX];

__device__ __forceinline__ bf2 bf2_of(unsigned int u) {
    bf2 r; memcpy(&r, &u, 4); return r;
}

__global__ __launch_bounds__(256) void fwd_kernel(
    const float* __restrict__ logits, const float* __restrict__ trans,
    const float* __restrict__ st, const float* __restrict__ en,
    const int* __restrict__ tags, const int* __restrict__ mask,
    int B, int K) {
    const int T = T_FIXED;
    const int lane = threadIdx.x & 31;
    const int warp = threadIdx.x >> 5;
    const int b = blockIdx.x * NW + warp;
    // p as bf16x2 i-pairs: pair k = (p_{2k}, p_{2k+1}); 32 pairs (26 used)
    __shared__ __align__(16) bf2 psh[NW][2][32];
    if (b >= B) return;

    // This lane owns output columns j0=2*lane, j1=2*lane+1.
    const int o2 = 2 * lane;
    const bool valid = (o2 < K);          // K even: both cols valid iff o2<K
    const int jc = valid ? o2 : 0;

    // E columns in bf16x2 registers: EA[k]=(E[2k][j0],E[2k+1][j0]), EB for j1.
    bf2 EA[NK2], EB[NK2];
#pragma unroll
    for (int k = 0; k < NK2; k++) {
        int i0 = 2 * k, i1 = 2 * k + 1;
        int i0c = (i0 < K) ? i0 : 0, i1c = (i1 < K) ? i1 : 0;
        bool v0 = valid && (i0 < K), v1 = valid && (i1 < K);
        float a0 = v0 ? __expf(__ldg(trans + i0c * K + jc)) : 0.f;
        float a1 = v1 ? __expf(__ldg(trans + i1c * K + jc)) : 0.f;
        float b0 = v0 ? __expf(__ldg(trans + i0c * K + jc + 1)) : 0.f;
        float b1 = v1 ? __expf(__ldg(trans + i1c * K + jc + 1)) : 0.f;
        EA[k] = __floats2bfloat162_rn(a0, a1);
        EB[k] = __floats2bfloat162_rn(b0, b1);
    }
    const float es0 = valid ? __expf(st[jc]) : 0.f;
    const float es1 = valid ? __expf(st[jc + 1]) : 0.f;
    const float ee0 = valid ? __expf(en[jc]) : 0.f;
    const float ee1 = valid ? __expf(en[jc + 1]) : 0.f;

    const float* lrow = logits + (size_t)b * T * K;
    const int* mrow = mask + (size_t)b * T;

    bf2* const p0 = psh[warp][0];
    bf2* const p1 = psh[warp][1];

    // t = 0 (fp32 w; pad lanes: es==0 -> w==0 forever, E cols 0 -> stay 0)
    float w0, w1;
    {
        float2 e0 = *(const float2*)(lrow + jc);
        w0 = es0 * __expf(e0.x);
        w1 = es1 * __expf(e0.y);
    }
    p0[lane] = __floats2bfloat162_rn(w0, w1);   // lane l writes pair l
    float C = 0.f;
    __syncwarp();

    // depth-4 prefetch rings in static register slots
    float2 e0s = *(const float2*)(lrow + (size_t)1 * K + jc);
    float2 e1s = *(const float2*)(lrow + (size_t)2 * K + jc);
    float2 e2s = *(const float2*)(lrow + (size_t)3 * K + jc);
    float2 e3s = *(const float2*)(lrow + (size_t)4 * K + jc);
    int m0s = mrow[1], m1s = mrow[2], m2s = mrow[3], m3s = mrow[4];

#define ACCK(word, k)                                                          \
    {                                                                          \
        bf2 pv_ = bf2_of(word);                                                \
        if ((k) & 1) { aA1 = __hfma2(pv_, EA[k], aA1);                         \
                       aB1 = __hfma2(pv_, EB[k], aB1); }                       \
        else         { aA0 = __hfma2(pv_, EA[k], aA0);                         \
                       aB0 = __hfma2(pv_, EB[k], aB0); }                       \
    }

#define STEP(tt, ESLOT, MSLOT, RB, WB)                                         \
    {                                                                          \
        const int t_ = (tt);                                                   \
        float2 e_ = ESLOT;                                                     \
        int m_ = MSLOT;                                                        \
        if (t_ + 4 < T) {                                                      \
            ESLOT = *(const float2*)(lrow + (size_t)(t_ + 4) * K + jc);        \
            MSLOT = mrow[t_ + 4];                                              \
        }                                                                      \
        float x0_ = __expf(e_.x), x1_ = __expf(e_.y);                          \
        const uint4* rb4_ = (const uint4*)(RB);                                \
        uint4 q0 = rb4_[0], q1 = rb4_[1], q2 = rb4_[2];                        \
        uint4 q3 = rb4_[3], q4 = rb4_[4], q5 = rb4_[5];                        \
        uint2 q6 = *(const uint2*)(rb4_ + 6);                                  \
        bf2 aA0 = __floats2bfloat162_rn(0.f, 0.f), aA1 = aA0;                  \
        bf2 aB0 = aA0, aB1 = aA0;                                              \
        ACCK(q0.x, 0)  ACCK(q0.y, 1)  ACCK(q0.z, 2)  ACCK(q0.w, 3)             \
        ACCK(q1.x, 4)  ACCK(q1.y, 5)  ACCK(q1.z, 6)  ACCK(q1.w, 7)             \
        ACCK(q2.x, 8)  ACCK(q2.y, 9)  ACCK(q2.z, 10) ACCK(q2.w, 11)            \
        ACCK(q3.x, 12) ACCK(q3.y, 13) ACCK(q3.z, 14) ACCK(q3.w, 15)            \
        ACCK(q4.x, 16) ACCK(q4.y, 17) ACCK(q4.z, 18) ACCK(q4.w, 19)            \
        ACCK(q5.x, 20) ACCK(q5.y, 21) ACCK(q5.z, 22) ACCK(q5.w, 23)            \
        ACCK(q6.x, 24) ACCK(q6.y, 25)                                          \
        bf2 sA_ = __hadd2(aA0, aA1);                                           \
        bf2 sB_ = __hadd2(aB0, aB1);                                           \
        float nw0_ = (__low2float(sA_) + __high2float(sA_)) * x0_;             \
        float nw1_ = (__low2float(sB_) + __high2float(sB_)) * x1_;             \
        w0 = m_ ? nw0_ : w0;                                                   \
        w1 = m_ ? nw1_ : w1;                                                   \
        if ((t_ & 7) == 7) {                                                   \
            float sr_ = w0 + w1;                                               \
            _Pragma("unroll")                                                  \
            for (int off = 16; off > 0; off >>= 1)                             \
                sr_ += __shfl_xor_sync(0xffffffffu, sr_, off);                 \
            C += __logf(sr_);                                                  \
            float inv_ = __frcp_rn(sr_);                                       \
            w0 *= inv_; w1 *= inv_;                                            \
        }                                                                      \
        (WB)[lane] = __floats2bfloat162_rn(w0, w1);                            \
        __syncwarp();                                                          \
    }

    int t = 1;
    for (; t + 3 < T; t += 4) {          // t odd at loop head: parity static
        STEP(t + 0, e0s, m0s, p0, p1)
        STEP(t + 1, e1s, m1s, p1, p0)
        STEP(t + 2, e2s, m2s, p0, p1)
        STEP(t + 3, e3s, m3s, p1, p0)
    }
    if (t + 2 < T) {                      // T=512: tail t = 509,510,511
        STEP(t + 0, e0s, m0s, p0, p1)
        STEP(t + 1, e1s, m1s, p1, p0)
        STEP(t + 2, e2s, m2s, p0, p1)
    }
#undef STEP
#undef ACCK

    // den = C + log( sum_j w[j] * exp(end[j]) )   (fp32)
    float sr = w0 * ee0 + w1 * ee1;
#pragma unroll
    for (int off = 16; off > 0; off >>= 1)
        sr += __shfl_xor_sync(0xffffffffu, sr, off);
    const float den = C + __logf(sr);

    // ---- fused numerator (exact fp32) ----
    const int* trow = tags + (size_t)b * T;
    float acc = 0.f;
    int msum = 0;
    for (int tt = lane; tt < T; tt += 32) {
        int tg = trow[tt];
        int mi = mrow[tt];
        float mf = (float)mi;
        msum += mi;
        if (tt >= 1)     acc += __ldg(trans + trow[tt - 1] * K + tg) * mf;
        if (tt < T - 1)  acc += lrow[(size_t)tt * K + tg] * mf;
    }
#pragma unroll
    for (int off = 16; off > 0; off >>= 1) {
        acc  += __shfl_xor_sync(0xffffffffu, acc, off);
        msum += __shfl_xor_sync(0xffffffffu, msum, off);
    }
    if (lane == 0) {
        int last = msum - 1;
        if (last < 0) last += T;            // jnp wrap-around on index -1
        int lt = trow[last];
        float sc = acc + st[trow[0]] + en[lt]
                 + lrow[(size_t)(T - 1) * K + lt] * (float)mrow[T - 1];
        g_res[b] = sc - den;
    }
}

__global__ void reduce_kernel(float* __restrict__ out, int B) {
    __shared__ double sd[256];
    int tid = threadIdx.x;
    double s = 0.0;
    for (int i = tid; i < B; i += 256) s += (double)g_res[i];
    sd[tid] = s;
    __syncthreads();
    for (int k = 128; k > 0; k >>= 1) {
        if (tid < k) sd[tid] += sd[tid + k];
        __syncthreads();
    }
    if (tid == 0) out[0] = (float)sd[0];
}

extern "C" void kernel_launch(void* const* d_in, const int* in_sizes, int n_in,
                              void* d_out, int out_size) {
    const float* logits = (const float*)d_in[0];
    const float* trans  = (const float*)d_in[1];
    const float* st     = (const float*)d_in[2];
    const float* en     = (const float*)d_in[3];
    const int*   tags   = (const int*)d_in[4];
    const int*   mask   = (const int*)d_in[5];

    int K  = in_sizes[2];        // 50
    int BT = in_sizes[4];        // B*T
    int B  = BT / T_FIXED;       // 1024

    fwd_kernel<<<(B + NW - 1) / NW, 32 * NW>>>(logits, trans, st, en, tags, mask, B, K);
    reduce_kernel<<<1, 256>>>((float*)d_out, B);
}